// round 12
// baseline (speedup 1.0000x reference)
#include <cuda_runtime.h>
#include <cuda_fp16.h>
#include <cstdint>

// ---------------- problem constants ----------------
#define B_SZ   2048
#define IN_F   1024
#define N_C    64
#define E_SZ   128
#define O_SZ   256
#define TM     64            // CTA M-tile (2 CTAs/SM)
#define KT     64            // fp16 k per chunk -> 128B rows
#define NCHUNK (IN_F / KT)   // 16
#define SLOPE  0.01f

// ---------------- scratch (static device globals) ----------------
__device__ __half g_Xh[B_SZ * IN_F];                    // fp16, k-permuted
__device__ __half g_Wh[(size_t)N_C * O_SZ * IN_F];      // [n][o][k] fp16, k-permuted

// ---------------- helpers ----------------
__device__ __forceinline__ uint32_t smem_u32(const void* p) {
    uint32_t a;
    asm("{ .reg .u64 t; cvta.to.shared.u64 t, %1; cvt.u32.u64 %0, t; }" : "=r"(a) : "l"(p));
    return a;
}
__device__ __forceinline__ void cp16(uint32_t dst, const void* src) {
    asm volatile("cp.async.cg.shared.global [%0], [%1], 16;" :: "r"(dst), "l"(src) : "memory");
}
__device__ __forceinline__ void lds4(uint32_t addr, uint32_t& x, uint32_t& y,
                                     uint32_t& z, uint32_t& w) {
    asm volatile("ld.shared.v4.b32 {%0,%1,%2,%3}, [%4];"
                 : "=r"(x), "=r"(y), "=r"(z), "=r"(w) : "r"(addr));
}
__device__ __forceinline__ void mma_f16(float* d, uint32_t a0, uint32_t a1,
                                        uint32_t a2, uint32_t a3,
                                        uint32_t b0, uint32_t b1) {
    asm volatile(
        "mma.sync.aligned.m16n8k16.row.col.f32.f16.f16.f32 "
        "{%0,%1,%2,%3}, {%4,%5,%6,%7}, {%8,%9}, {%0,%1,%2,%3};"
        : "+f"(d[0]), "+f"(d[1]), "+f"(d[2]), "+f"(d[3])
        : "r"(a0), "r"(a1), "r"(a2), "r"(a3), "r"(b0), "r"(b1));
}

// smem tile addressing: 128B rows, 8 x 16B segs, 1-bit XOR swizzle on seg bit2.
// Stepping seg by +4 (k-block toggle) flips only address bit 6 for both row
// parities -> runtime blk step is (addr ^ 0x40); rows contribute bits >= 7.
__device__ __forceinline__ uint32_t tile_off(int row, int seg) {
    return (uint32_t)(row * 128 + ((seg ^ ((row & 1) << 2)) << 4));
}

// ---------------- fused prep kernel ----------------
// k-permutation within each aligned 32-block: position p holds
// k = 16*((p>>2)&1) + 8*((p>>1)&1) + 2*(p>>3) + (p&1).
//
// grid (8, 8, 65), block (32, 8) = 256 threads:
//   z == 0 : X round+permute (64 blocks x 4 chunks/thread), scheduled FIRST
//            so it overlaps under the W wave instead of tailing it.
//   z >= 1 : concept n = z-1; W transpose [n][k][o] -> [n][o][kperm] with
//            128k x 32o tiles (4 float4 reads + 2 uint4 stores per thread
//            -> MLP 4 on the read side, full 128B store lines per warp).
__global__ void conv_prep(const float* __restrict__ x, const float* __restrict__ W) {
    const int tx = threadIdx.x, ty = threadIdx.y;   // 32 x 8
    const int u = ty * 32 + tx;
    if (blockIdx.z == 0) {
        const int blk = blockIdx.y * 8 + blockIdx.x;    // 0..63
#pragma unroll
        for (int ch = 0; ch < 4; ++ch) {
            const int c = blk * 1024 + ch * 256 + u;    // 32-float chunk id
            const float4* src = reinterpret_cast<const float4*>(x) + (size_t)c * 8;
            float v[32];
#pragma unroll
            for (int f = 0; f < 8; ++f) {
                float4 t = src[f];
                v[4*f] = t.x; v[4*f+1] = t.y; v[4*f+2] = t.z; v[4*f+3] = t.w;
            }
            __half o[32];
#pragma unroll
            for (int p = 0; p < 32; ++p) {
                const int k = 16 * ((p >> 2) & 1) + 8 * ((p >> 1) & 1)
                            + 2 * (p >> 3) + (p & 1);
                o[p] = __float2half_rn(v[k]);
            }
            uint4* dst = reinterpret_cast<uint4*>(g_Xh + (size_t)c * 32);
#pragma unroll
            for (int f = 0; f < 4; ++f)
                dst[f] = reinterpret_cast<const uint4*>(o)[f];
        }
        return;
    }
    // ---- W: 128 k x 32 o tile ----
    __shared__ float tile[128][33];
    const int n  = blockIdx.z - 1;
    const int k0 = blockIdx.x * 128;                // 8 k-blocks
    const int o0 = blockIdx.y * 32;                 // 8 o-blocks
    const float* src = W + ((size_t)n * IN_F + k0) * O_SZ + o0;
    // read 128 rows x 32 floats: 4 float4 per thread, all issued before sync
#pragma unroll
    for (int j = 0; j < 4; ++j) {
        const int idx = u + 256 * j;                // 0..1023
        const int row = idx >> 3, f4 = idx & 7;
        const float4 v = *reinterpret_cast<const float4*>(
            src + (size_t)row * O_SZ + f4 * 4);
        tile[row][f4 * 4 + 0] = v.x;
        tile[row][f4 * 4 + 1] = v.y;
        tile[row][f4 * 4 + 2] = v.z;
        tile[row][f4 * 4 + 3] = v.w;
    }
    __syncthreads();
    // write: o = u>>3 (32 values), seg = u&7; two 64k-subtiles per thread
    const int o = u >> 3, seg = u & 7;
    const int h = seg >> 2, q = seg & 3;
    __half* orow = g_Wh + ((size_t)n * O_SZ + o0 + o) * IN_F + k0;
#pragma unroll
    for (int kt = 0; kt < 2; ++kt) {
        const int kb = kt * 64 + 32 * h + 2 * q;
        __half hv[8];
        hv[0] = __float2half_rn(tile[kb][o]);
        hv[1] = __float2half_rn(tile[kb + 1][o]);
        hv[2] = __float2half_rn(tile[kb + 8][o]);
        hv[3] = __float2half_rn(tile[kb + 9][o]);
        hv[4] = __float2half_rn(tile[kb + 16][o]);
        hv[5] = __float2half_rn(tile[kb + 17][o]);
        hv[6] = __float2half_rn(tile[kb + 24][o]);
        hv[7] = __float2half_rn(tile[kb + 25][o]);
        *reinterpret_cast<uint4*>(orow + kt * 64 + seg * 8) =
            *reinterpret_cast<const uint4*>(hv);
    }
}

// ---------------- GEMM + fused epilogue ----------------
// 256 threads = 8 warps as 2M x 4N, warp tile 32x64, CTA tile 64x256.
// 2 CTAs/SM (4 warps/SMSP from independent CTAs).
// dyn smem: double buffer { A 64x128B (8K), B 256x128B (32K) } = 2 x 40K
//           epilogue overlay: nctx[64][132] at 0; sdot[64][4] at 81920; pv at 82944
#define A_BYTES    8192
#define BUF_BYTES  40960
#define SD_OFF     81920
#define PV_OFF     82944
#define SMEM_TOTAL 83200

__global__ __launch_bounds__(256, 2)
void concept_mma_kernel(const float* __restrict__ bc,
                        const float* __restrict__ wp,
                        const float* __restrict__ bp,
                        float* __restrict__ out)
{
    extern __shared__ char smem[];
    const uint32_t sb = smem_u32(smem);
    const int tid = threadIdx.x, lane = tid & 31, wid = tid >> 5;
    const int wn = wid & 3, wm = wid >> 2;     // 4 N-warps x 2 M-warps
    const int n = blockIdx.y, m0 = blockIdx.x * TM;
    const int lq = lane & 3, lr = lane >> 2;

    const __half* Ag = g_Xh + (size_t)m0 * IN_F;
    const __half* Bg = g_Wh + (size_t)n * O_SZ * IN_F;

    float acc[2][8][4];
#pragma unroll
    for (int a = 0; a < 2; ++a)
#pragma unroll
        for (int b = 0; b < 8; ++b)
#pragma unroll
            for (int c = 0; c < 4; ++c) acc[a][b][c] = 0.f;

    // ---- hoisted addressing ----
    const int crow = tid >> 3, cseg = tid & 7;
    const uint32_t stOff = tile_off(crow, cseg);
    const size_t gOff = (size_t)crow * IN_F + cseg * 8;
    const uint32_t offA = tile_off(wm * 32 + lr, lq);
    const uint32_t offB = tile_off(wn * 64 + lr, lq);

    // ---- prologue: chunk 0 into buffer 0 ----
    {
        const uint32_t ab = sb, bb = sb + A_BYTES;
#pragma unroll
        for (int j = 0; j < 2; ++j)
            cp16(ab + stOff + j * 4096, Ag + gOff + (size_t)j * 32 * IN_F);
#pragma unroll
        for (int j = 0; j < 8; ++j)
            cp16(bb + stOff + j * 4096, Bg + gOff + (size_t)j * 32 * IN_F);
        asm volatile("cp.async.commit_group;" ::: "memory");
        asm volatile("cp.async.wait_group 0;" ::: "memory");
        __syncthreads();
    }

    // unroll 2: (t&1)/((t+1)&1) become compile-time -> buffer bases immediate
#pragma unroll 2
    for (int t = 0; t < NCHUNK; ++t) {
        if (t + 1 < NCHUNK) {   // prefetch next chunk into other buffer
            const uint32_t ab = sb + ((t + 1) & 1) * BUF_BYTES, bb = ab + A_BYTES;
            const __half* An = Ag + (t + 1) * KT + gOff;
            const __half* Bn = Bg + (t + 1) * KT + gOff;
#pragma unroll
            for (int j = 0; j < 2; ++j)
                cp16(ab + stOff + j * 4096, An + (size_t)j * 32 * IN_F);
#pragma unroll
            for (int j = 0; j < 8; ++j)
                cp16(bb + stOff + j * 4096, Bn + (size_t)j * 32 * IN_F);
            asm volatile("cp.async.commit_group;" ::: "memory");
        }

        const uint32_t aB = sb + (t & 1) * BUF_BYTES + offA;
        const uint32_t bB = sb + (t & 1) * BUF_BYTES + A_BYTES + offB;
#pragma unroll
        for (int blk = 0; blk < 2; ++blk) {
            const uint32_t bx = blk ? 0x40u : 0u;
            uint32_t a2[2][8];              // both 16-row A tiles for this blk
#pragma unroll
            for (int mt = 0; mt < 2; ++mt) {
                lds4((aB ^ bx) + mt * 2048,
                     a2[mt][0], a2[mt][1], a2[mt][2], a2[mt][3]);
                lds4((aB ^ bx) + mt * 2048 + 1024,
                     a2[mt][4], a2[mt][5], a2[mt][6], a2[mt][7]);
            }
#pragma unroll
            for (int nh = 0; nh < 2; ++nh) {
                uint32_t bf[16];
#pragma unroll
                for (int nt = 0; nt < 4; ++nt)
                    lds4((bB ^ bx) + (nh * 4 + nt) * 1024,
                         bf[nt*4+0], bf[nt*4+1], bf[nt*4+2], bf[nt*4+3]);
#pragma unroll
                for (int mt = 0; mt < 2; ++mt)
#pragma unroll
                    for (int s = 0; s < 2; ++s)
#pragma unroll
                        for (int nt = 0; nt < 4; ++nt)
                            mma_f16(acc[mt][nh * 4 + nt],
                                    a2[mt][2*s], a2[mt][4 + 2*s],
                                    a2[mt][2*s + 1], a2[mt][4 + 2*s + 1],
                                    bf[nt*4 + 2*s], bf[nt*4 + 2*s + 1]);
            }
        }
        asm volatile("cp.async.wait_group 0;" ::: "memory");
        __syncthreads();
    }

    // ---------------- fused epilogue ----------------
    const float* bcn = bc + (size_t)n * O_SZ;
    float* nctx = reinterpret_cast<float*>(smem);               // [64][132]
    float* sdot = reinterpret_cast<float*>(smem + SD_OFF);      // [64][4]
    float* pv   = reinterpret_cast<float*>(smem + PV_OFF);      // [64]

    float dotr[2][2] = {{0.f, 0.f}, {0.f, 0.f}};
#pragma unroll
    for (int mt = 0; mt < 2; ++mt) {
#pragma unroll
        for (int nt = 0; nt < 8; ++nt) {
            const int colb = wn * 64 + nt * 8 + 2 * lq;
            const float b0v = bcn[colb], b1v = bcn[colb + 1];
            const float w0 = wp[colb],  w1 = wp[colb + 1];
#pragma unroll
            for (int rr = 0; rr < 2; ++rr) {
                float v0 = acc[mt][nt][2*rr]     + b0v;
                float v1 = acc[mt][nt][2*rr + 1] + b1v;
                v0 = (v0 >= 0.f) ? v0 : SLOPE * v0;
                v1 = (v1 >= 0.f) ? v1 : SLOPE * v1;
                acc[mt][nt][2*rr] = v0; acc[mt][nt][2*rr + 1] = v1;
                dotr[mt][rr] = fmaf(v0, w0, fmaf(v1, w1, dotr[mt][rr]));
            }
        }
    }
#pragma unroll
    for (int mt = 0; mt < 2; ++mt)
#pragma unroll
        for (int rr = 0; rr < 2; ++rr) {
            dotr[mt][rr] += __shfl_xor_sync(0xffffffffu, dotr[mt][rr], 1);
            dotr[mt][rr] += __shfl_xor_sync(0xffffffffu, dotr[mt][rr], 2);
        }
    if (lq == 0) {
#pragma unroll
        for (int mt = 0; mt < 2; ++mt)
#pragma unroll
            for (int rr = 0; rr < 2; ++rr) {
                const int row = wm * 32 + mt * 16 + lr + 8 * rr;
                sdot[row * 4 + wn] = dotr[mt][rr];
            }
    }
    if (wn >= 2) {   // stage negative half (cols 128..255) for the blend
#pragma unroll
        for (int mt = 0; mt < 2; ++mt)
#pragma unroll
            for (int nt = 0; nt < 8; ++nt) {
                const int row = wm * 32 + mt * 16 + lr;
                const int col = (wn - 2) * 64 + nt * 8 + 2 * lq;
                nctx[row * 132 + col]           = acc[mt][nt][0];
                nctx[row * 132 + col + 1]       = acc[mt][nt][1];
                nctx[(row + 8) * 132 + col]     = acc[mt][nt][2];
                nctx[(row + 8) * 132 + col + 1] = acc[mt][nt][3];
            }
    }
    __syncthreads();

    if (tid < TM) {
        const float s = sdot[tid * 4] + sdot[tid * 4 + 1]
                      + sdot[tid * 4 + 2] + sdot[tid * 4 + 3];
        const float p = 1.f / (1.f + expf(-(s + *bp)));
        pv[tid] = p;
        out[(size_t)B_SZ * N_C * E_SZ + (size_t)(m0 + tid) * N_C + n] = p;
    }
    __syncthreads();

    if (wn < 2) {    // blend + store c_emb (cols 0..127)
#pragma unroll
        for (int mt = 0; mt < 2; ++mt) {
#pragma unroll
            for (int rr = 0; rr < 2; ++rr) {
                const int row = wm * 32 + mt * 16 + lr + 8 * rr;
                const float p = pv[row];
                float* orow = out + ((size_t)(m0 + row) * N_C + n) * E_SZ;
#pragma unroll
                for (int nt = 0; nt < 8; ++nt) {
                    const int col = wn * 64 + nt * 8 + 2 * lq;
                    const float p0 = acc[mt][nt][2*rr], p1 = acc[mt][nt][2*rr + 1];
                    const float g0 = nctx[row * 132 + col];
                    const float g1 = nctx[row * 132 + col + 1];
                    *reinterpret_cast<float2*>(orow + col) =
                        make_float2(fmaf(p0 - g0, p, g0), fmaf(p1 - g1, p, g1));
                }
            }
        }
    }
}

// ---------------- launch ----------------
extern "C" void kernel_launch(void* const* d_in, const int* in_sizes, int n_in,
                              void* d_out, int out_size)
{
    const float* x  = (const float*)d_in[0];   // [2048,1024]
    const float* Wc = (const float*)d_in[1];   // [64,1024,256]
    const float* bc = (const float*)d_in[2];   // [64,256]
    const float* wp = (const float*)d_in[3];   // [256]
    const float* bp = (const float*)d_in[4];   // scalar
    float* out = (float*)d_out;

    cudaFuncSetAttribute(concept_mma_kernel,
                         cudaFuncAttributeMaxDynamicSharedMemorySize, SMEM_TOTAL);

    conv_prep<<<dim3(8, 8, 65), dim3(32, 8)>>>(x, Wc);
    concept_mma_kernel<<<dim3(B_SZ / TM, N_C), 256, SMEM_TOTAL>>>(bc, wp, bp, out);
}

// round 13
// speedup vs baseline: 1.1147x; 1.1147x over previous
#include <cuda_runtime.h>
#include <cuda_fp16.h>
#include <cstdint>

// ---------------- problem constants ----------------
#define B_SZ   2048
#define IN_F   1024
#define N_C    64
#define E_SZ   128
#define O_SZ   256
#define TM     64            // CTA M-tile (2 CTAs/SM)
#define KT     64            // fp16 k per chunk -> 128B rows
#define NCHUNK (IN_F / KT)   // 16
#define SLOPE  0.01f

// ---------------- scratch (static device globals) ----------------
__device__ __half g_Xh[B_SZ * IN_F];                    // fp16, k-permuted
__device__ __half g_Wh[(size_t)N_C * O_SZ * IN_F];      // [n][o][k] fp16, k-permuted

// ---------------- helpers ----------------
__device__ __forceinline__ uint32_t smem_u32(const void* p) {
    uint32_t a;
    asm("{ .reg .u64 t; cvta.to.shared.u64 t, %1; cvt.u32.u64 %0, t; }" : "=r"(a) : "l"(p));
    return a;
}
__device__ __forceinline__ void cp16(uint32_t dst, const void* src) {
    asm volatile("cp.async.cg.shared.global [%0], [%1], 16;" :: "r"(dst), "l"(src) : "memory");
}
__device__ __forceinline__ void lds4(uint32_t addr, uint32_t& x, uint32_t& y,
                                     uint32_t& z, uint32_t& w) {
    asm volatile("ld.shared.v4.b32 {%0,%1,%2,%3}, [%4];"
                 : "=r"(x), "=r"(y), "=r"(z), "=r"(w) : "r"(addr));
}
__device__ __forceinline__ void mma_f16(float* d, uint32_t a0, uint32_t a1,
                                        uint32_t a2, uint32_t a3,
                                        uint32_t b0, uint32_t b1) {
    asm volatile(
        "mma.sync.aligned.m16n8k16.row.col.f32.f16.f16.f32 "
        "{%0,%1,%2,%3}, {%4,%5,%6,%7}, {%8,%9}, {%0,%1,%2,%3};"
        : "+f"(d[0]), "+f"(d[1]), "+f"(d[2]), "+f"(d[3])
        : "r"(a0), "r"(a1), "r"(a2), "r"(a3), "r"(b0), "r"(b1));
}

// smem tile addressing: 128B rows, 8 x 16B segs, 1-bit XOR swizzle on seg bit2.
// Stepping seg by +4 (k-block toggle) flips only address bit 6 for both row
// parities -> runtime blk step is (addr ^ 0x40); rows contribute bits >= 7.
__device__ __forceinline__ uint32_t tile_off(int row, int seg) {
    return (uint32_t)(row * 128 + ((seg ^ ((row & 1) << 2)) << 4));
}

// ---------------- fused prep kernel (R12 version: MLP-4 W reads) ----------------
// k-permutation within each aligned 32-block: position p holds
// k = 16*((p>>2)&1) + 8*((p>>1)&1) + 2*(p>>3) + (p&1).
//
// grid (8, 8, 65), block (32, 8) = 256 threads:
//   z == 0 : X round+permute (64 blocks x 4 chunks/thread), scheduled FIRST
//            so it overlaps under the W wave instead of tailing it.
//   z >= 1 : concept n = z-1; W transpose [n][k][o] -> [n][o][kperm] with
//            128k x 32o tiles (4 float4 reads + 2 uint4 stores per thread).
__global__ void conv_prep(const float* __restrict__ x, const float* __restrict__ W) {
    const int tx = threadIdx.x, ty = threadIdx.y;   // 32 x 8
    const int u = ty * 32 + tx;
    if (blockIdx.z == 0) {
        const int blk = blockIdx.y * 8 + blockIdx.x;    // 0..63
#pragma unroll
        for (int ch = 0; ch < 4; ++ch) {
            const int c = blk * 1024 + ch * 256 + u;    // 32-float chunk id
            const float4* src = reinterpret_cast<const float4*>(x) + (size_t)c * 8;
            float v[32];
#pragma unroll
            for (int f = 0; f < 8; ++f) {
                float4 t = src[f];
                v[4*f] = t.x; v[4*f+1] = t.y; v[4*f+2] = t.z; v[4*f+3] = t.w;
            }
            __half o[32];
#pragma unroll
            for (int p = 0; p < 32; ++p) {
                const int k = 16 * ((p >> 2) & 1) + 8 * ((p >> 1) & 1)
                            + 2 * (p >> 3) + (p & 1);
                o[p] = __float2half_rn(v[k]);
            }
            uint4* dst = reinterpret_cast<uint4*>(g_Xh + (size_t)c * 32);
#pragma unroll
            for (int f = 0; f < 4; ++f)
                dst[f] = reinterpret_cast<const uint4*>(o)[f];
        }
        return;
    }
    // ---- W: 128 k x 32 o tile ----
    __shared__ float tile[128][33];
    const int n  = blockIdx.z - 1;
    const int k0 = blockIdx.x * 128;                // 8 k-blocks
    const int o0 = blockIdx.y * 32;                 // 8 o-blocks
    const float* src = W + ((size_t)n * IN_F + k0) * O_SZ + o0;
    // read 128 rows x 32 floats: 4 float4 per thread, all issued before sync
#pragma unroll
    for (int j = 0; j < 4; ++j) {
        const int idx = u + 256 * j;                // 0..1023
        const int row = idx >> 3, f4 = idx & 7;
        const float4 v = *reinterpret_cast<const float4*>(
            src + (size_t)row * O_SZ + f4 * 4);
        tile[row][f4 * 4 + 0] = v.x;
        tile[row][f4 * 4 + 1] = v.y;
        tile[row][f4 * 4 + 2] = v.z;
        tile[row][f4 * 4 + 3] = v.w;
    }
    __syncthreads();
    // write: o = u>>3 (32 values), seg = u&7; two 64k-subtiles per thread
    const int o = u >> 3, seg = u & 7;
    const int h = seg >> 2, q = seg & 3;
    __half* orow = g_Wh + ((size_t)n * O_SZ + o0 + o) * IN_F + k0;
#pragma unroll
    for (int kt = 0; kt < 2; ++kt) {
        const int kb = kt * 64 + 32 * h + 2 * q;
        __half hv[8];
        hv[0] = __float2half_rn(tile[kb][o]);
        hv[1] = __float2half_rn(tile[kb + 1][o]);
        hv[2] = __float2half_rn(tile[kb + 8][o]);
        hv[3] = __float2half_rn(tile[kb + 9][o]);
        hv[4] = __float2half_rn(tile[kb + 16][o]);
        hv[5] = __float2half_rn(tile[kb + 17][o]);
        hv[6] = __float2half_rn(tile[kb + 24][o]);
        hv[7] = __float2half_rn(tile[kb + 25][o]);
        *reinterpret_cast<uint4*>(orow + kt * 64 + seg * 8) =
            *reinterpret_cast<const uint4*>(hv);
    }
}

// ---------------- GEMM + fused epilogue (R11 version: 207.5us, no unroll pragma) ----------------
// 256 threads = 8 warps as 2M x 4N, warp tile 32x64, CTA tile 64x256.
// 2 CTAs/SM (4 warps/SMSP from independent CTAs).
// dyn smem: double buffer { A 64x128B (8K), B 256x128B (32K) } = 2 x 40K
//           epilogue overlay: nctx[64][132] at 0; sdot[64][4] at 81920; pv at 82944
#define A_BYTES    8192
#define BUF_BYTES  40960
#define SD_OFF     81920
#define PV_OFF     82944
#define SMEM_TOTAL 83200

__global__ __launch_bounds__(256, 2)
void concept_mma_kernel(const float* __restrict__ bc,
                        const float* __restrict__ wp,
                        const float* __restrict__ bp,
                        float* __restrict__ out)
{
    extern __shared__ char smem[];
    const uint32_t sb = smem_u32(smem);
    const int tid = threadIdx.x, lane = tid & 31, wid = tid >> 5;
    const int wn = wid & 3, wm = wid >> 2;     // 4 N-warps x 2 M-warps
    const int n = blockIdx.y, m0 = blockIdx.x * TM;
    const int lq = lane & 3, lr = lane >> 2;

    const __half* Ag = g_Xh + (size_t)m0 * IN_F;
    const __half* Bg = g_Wh + (size_t)n * O_SZ * IN_F;

    float acc[2][8][4];
#pragma unroll
    for (int a = 0; a < 2; ++a)
#pragma unroll
        for (int b = 0; b < 8; ++b)
#pragma unroll
            for (int c = 0; c < 4; ++c) acc[a][b][c] = 0.f;

    // ---- hoisted addressing ----
    const int crow = tid >> 3, cseg = tid & 7;
    const uint32_t stOff = tile_off(crow, cseg);
    const size_t gOff = (size_t)crow * IN_F + cseg * 8;
    const uint32_t offA = tile_off(wm * 32 + lr, lq);
    const uint32_t offB = tile_off(wn * 64 + lr, lq);

    // ---- prologue: chunk 0 into buffer 0 ----
    {
        const uint32_t ab = sb, bb = sb + A_BYTES;
#pragma unroll
        for (int j = 0; j < 2; ++j)
            cp16(ab + stOff + j * 4096, Ag + gOff + (size_t)j * 32 * IN_F);
#pragma unroll
        for (int j = 0; j < 8; ++j)
            cp16(bb + stOff + j * 4096, Bg + gOff + (size_t)j * 32 * IN_F);
        asm volatile("cp.async.commit_group;" ::: "memory");
        asm volatile("cp.async.wait_group 0;" ::: "memory");
        __syncthreads();
    }

    for (int t = 0; t < NCHUNK; ++t) {
        if (t + 1 < NCHUNK) {   // prefetch next chunk into other buffer
            const uint32_t ab = sb + ((t + 1) & 1) * BUF_BYTES, bb = ab + A_BYTES;
            const __half* An = Ag + (t + 1) * KT + gOff;
            const __half* Bn = Bg + (t + 1) * KT + gOff;
#pragma unroll
            for (int j = 0; j < 2; ++j)
                cp16(ab + stOff + j * 4096, An + (size_t)j * 32 * IN_F);
#pragma unroll
            for (int j = 0; j < 8; ++j)
                cp16(bb + stOff + j * 4096, Bn + (size_t)j * 32 * IN_F);
            asm volatile("cp.async.commit_group;" ::: "memory");
        }

        const uint32_t aB = sb + (t & 1) * BUF_BYTES + offA;
        const uint32_t bB = sb + (t & 1) * BUF_BYTES + A_BYTES + offB;
#pragma unroll
        for (int blk = 0; blk < 2; ++blk) {
            const uint32_t bx = blk ? 0x40u : 0u;
            uint32_t a2[2][8];              // both 16-row A tiles for this blk
#pragma unroll
            for (int mt = 0; mt < 2; ++mt) {
                lds4((aB ^ bx) + mt * 2048,
                     a2[mt][0], a2[mt][1], a2[mt][2], a2[mt][3]);
                lds4((aB ^ bx) + mt * 2048 + 1024,
                     a2[mt][4], a2[mt][5], a2[mt][6], a2[mt][7]);
            }
#pragma unroll
            for (int nh = 0; nh < 2; ++nh) {
                uint32_t bf[16];
#pragma unroll
                for (int nt = 0; nt < 4; ++nt)
                    lds4((bB ^ bx) + (nh * 4 + nt) * 1024,
                         bf[nt*4+0], bf[nt*4+1], bf[nt*4+2], bf[nt*4+3]);
#pragma unroll
                for (int mt = 0; mt < 2; ++mt)
#pragma unroll
                    for (int s = 0; s < 2; ++s)
#pragma unroll
                        for (int nt = 0; nt < 4; ++nt)
                            mma_f16(acc[mt][nh * 4 + nt],
                                    a2[mt][2*s], a2[mt][4 + 2*s],
                                    a2[mt][2*s + 1], a2[mt][4 + 2*s + 1],
                                    bf[nt*4 + 2*s], bf[nt*4 + 2*s + 1]);
            }
        }
        asm volatile("cp.async.wait_group 0;" ::: "memory");
        __syncthreads();
    }

    // ---------------- fused epilogue ----------------
    const float* bcn = bc + (size_t)n * O_SZ;
    float* nctx = reinterpret_cast<float*>(smem);               // [64][132]
    float* sdot = reinterpret_cast<float*>(smem + SD_OFF);      // [64][4]
    float* pv   = reinterpret_cast<float*>(smem + PV_OFF);      // [64]

    float dotr[2][2] = {{0.f, 0.f}, {0.f, 0.f}};
#pragma unroll
    for (int mt = 0; mt < 2; ++mt) {
#pragma unroll
        for (int nt = 0; nt < 8; ++nt) {
            const int colb = wn * 64 + nt * 8 + 2 * lq;
            const float b0v = bcn[colb], b1v = bcn[colb + 1];
            const float w0 = wp[colb],  w1 = wp[colb + 1];
#pragma unroll
            for (int rr = 0; rr < 2; ++rr) {
                float v0 = acc[mt][nt][2*rr]     + b0v;
                float v1 = acc[mt][nt][2*rr + 1] + b1v;
                v0 = (v0 >= 0.f) ? v0 : SLOPE * v0;
                v1 = (v1 >= 0.f) ? v1 : SLOPE * v1;
                acc[mt][nt][2*rr] = v0; acc[mt][nt][2*rr + 1] = v1;
                dotr[mt][rr] = fmaf(v0, w0, fmaf(v1, w1, dotr[mt][rr]));
            }
        }
    }
#pragma unroll
    for (int mt = 0; mt < 2; ++mt)
#pragma unroll
        for (int rr = 0; rr < 2; ++rr) {
            dotr[mt][rr] += __shfl_xor_sync(0xffffffffu, dotr[mt][rr], 1);
            dotr[mt][rr] += __shfl_xor_sync(0xffffffffu, dotr[mt][rr], 2);
        }
    if (lq == 0) {
#pragma unroll
        for (int mt = 0; mt < 2; ++mt)
#pragma unroll
            for (int rr = 0; rr < 2; ++rr) {
                const int row = wm * 32 + mt * 16 + lr + 8 * rr;
                sdot[row * 4 + wn] = dotr[mt][rr];
            }
    }
    if (wn >= 2) {   // stage negative half (cols 128..255) for the blend
#pragma unroll
        for (int mt = 0; mt < 2; ++mt)
#pragma unroll
            for (int nt = 0; nt < 8; ++nt) {
                const int row = wm * 32 + mt * 16 + lr;
                const int col = (wn - 2) * 64 + nt * 8 + 2 * lq;
                nctx[row * 132 + col]           = acc[mt][nt][0];
                nctx[row * 132 + col + 1]       = acc[mt][nt][1];
                nctx[(row + 8) * 132 + col]     = acc[mt][nt][2];
                nctx[(row + 8) * 132 + col + 1] = acc[mt][nt][3];
            }
    }
    __syncthreads();

    if (tid < TM) {
        const float s = sdot[tid * 4] + sdot[tid * 4 + 1]
                      + sdot[tid * 4 + 2] + sdot[tid * 4 + 3];
        const float p = 1.f / (1.f + expf(-(s + *bp)));
        pv[tid] = p;
        out[(size_t)B_SZ * N_C * E_SZ + (size_t)(m0 + tid) * N_C + n] = p;
    }
    __syncthreads();

    if (wn < 2) {    // blend + store c_emb (cols 0..127)
#pragma unroll
        for (int mt = 0; mt < 2; ++mt) {
#pragma unroll
            for (int rr = 0; rr < 2; ++rr) {
                const int row = wm * 32 + mt * 16 + lr + 8 * rr;
                const float p = pv[row];
                float* orow = out + ((size_t)(m0 + row) * N_C + n) * E_SZ;
#pragma unroll
                for (int nt = 0; nt < 8; ++nt) {
                    const int col = wn * 64 + nt * 8 + 2 * lq;
                    const float p0 = acc[mt][nt][2*rr], p1 = acc[mt][nt][2*rr + 1];
                    const float g0 = nctx[row * 132 + col];
                    const float g1 = nctx[row * 132 + col + 1];
                    *reinterpret_cast<float2*>(orow + col) =
                        make_float2(fmaf(p0 - g0, p, g0), fmaf(p1 - g1, p, g1));
                }
            }
        }
    }
}

// ---------------- launch ----------------
extern "C" void kernel_launch(void* const* d_in, const int* in_sizes, int n_in,
                              void* d_out, int out_size)
{
    const float* x  = (const float*)d_in[0];   // [2048,1024]
    const float* Wc = (const float*)d_in[1];   // [64,1024,256]
    const float* bc = (const float*)d_in[2];   // [64,256]
    const float* wp = (const float*)d_in[3];   // [256]
    const float* bp = (const float*)d_in[4];   // scalar
    float* out = (float*)d_out;

    cudaFuncSetAttribute(concept_mma_kernel,
                         cudaFuncAttributeMaxDynamicSharedMemorySize, SMEM_TOTAL);

    conv_prep<<<dim3(8, 8, 65), dim3(32, 8)>>>(x, Wc);
    concept_mma_kernel<<<dim3(B_SZ / TM, N_C), 256, SMEM_TOTAL>>>(bc, wp, bp, out);
}